// round 9
// baseline (speedup 1.0000x reference)
#include <cuda_runtime.h>
#include <math.h>

#define BB 2
#define MM 8192
#define NN 8192
#define TPB 256
#define QB (MM/TPB)            // 32 query blocks
#define NSPLIT 8               // candidate splits
#define QPT 8                  // queries per thread (8 warps x 32 lanes)
#define CPB 1024               // candidates per block tile
#define PPB (CPB/2)            // pairs per block tile = 512
#define NW 8
#define CPW (CPB/NW)           // candidates per warp = 128
#define PPW (PPB/NW)           // pairs per warp = 64
#define CHUNK_P 4              // pairs per tracking chunk (8 candidates)
#define NCHUNK (PPW/CHUNK_P)   // 16
#define NGRP 8                 // 4-lane groups per warp
#define NPAIR_G (BB*NN/2)      // 8192 candidate pairs globally
#define NLOSSM (BB*MM/8)       // 2048
#define NLOSSN (NPAIR_G/TPB)   // 32
#define NLOSS  (NLOSSM+NLOSSN)

// ---- scratch (owned slots, no init needed) ----------------------------------
__device__ unsigned long long g_part_m[NSPLIT * BB * MM];     // (dsq<<32)|idx
__device__ float2             g_part_n[QB * NGRP * NPAIR_G];  // max-v per group
__device__ float              g_lsum[NLOSS];

// ---- packed f32x2 helpers ---------------------------------------------------
__device__ __forceinline__ unsigned long long pk2(float lo, float hi) {
    unsigned long long r;
    asm("mov.b64 %0, {%1,%2};" : "=l"(r) : "f"(lo), "f"(hi));
    return r;
}
__device__ __forceinline__ float lo32(unsigned long long v) {
    return __uint_as_float((unsigned)(v & 0xFFFFFFFFull));
}
// v = qx*sx + qy*sy + qz*sz + nb + nqq on both halves (nb=-|c|^2/2, nqq=-|q|^2/2)
__device__ __forceinline__ void ffma2v(
    float& v0, float& v1,
    unsigned long long qz2, unsigned long long sz2, unsigned long long nb2,
    unsigned long long qy2, unsigned long long sy2,
    unsigned long long qx2, unsigned long long sx2, unsigned long long nqq2) {
    asm("{\n\t.reg .b64 t;\n\t"
        "fma.rn.f32x2 t, %2, %3, %4;\n\t"
        "fma.rn.f32x2 t, %5, %6, t;\n\t"
        "fma.rn.f32x2 t, %7, %8, t;\n\t"
        "add.rn.f32x2 t, t, %9;\n\t"
        "mov.b64 {%0,%1}, t;\n\t}"
        : "=f"(v0), "=f"(v1)
        : "l"(qz2), "l"(sz2), "l"(nb2), "l"(qy2), "l"(sy2),
          "l"(qx2), "l"(sx2), "l"(nqq2));
}

// ---- single shared-matrix scan: queries = out_xyz, candidates = in_xyz ------
__global__ void __launch_bounds__(TPB, 2)
dist_kernel(const float* __restrict__ out_xyz,
            const float* __restrict__ in_xyz) {
    __shared__ unsigned long long sX[PPB], sY[PPB], sZ[PPB], sNB[PPB];
    __shared__ unsigned long long skey[TPB];

    const int tid = threadIdx.x;
    const int lane = tid & 31, w = tid >> 5;
    const int qb = blockIdx.x;
    const int split = blockIdx.y;
    const int b = blockIdx.z;
    const int cbase = split * CPB;
    const int qbase = qb * TPB;

    skey[tid] = 0xFFFFFFFFFFFFFFFFull;

    // candidate tile (in_xyz), packed two-per-u64 (even, odd)
    for (int p = tid; p < PPB; p += TPB) {
        const float2* cp =
            (const float2*)(in_xyz + ((size_t)b * NN + cbase + 2 * p) * 3);
        float2 f0 = __ldg(cp + 0);   // x0 y0
        float2 f1 = __ldg(cp + 1);   // z0 x1
        float2 f2 = __ldg(cp + 2);   // y1 z1
        float n0 = -0.5f * fmaf(f0.x, f0.x, fmaf(f0.y, f0.y, f1.x * f1.x));
        float n1 = -0.5f * fmaf(f1.y, f1.y, fmaf(f2.x, f2.x, f2.y * f2.y));
        sX[p]  = pk2(f0.x, f1.y);
        sY[p]  = pk2(f0.y, f2.x);
        sZ[p]  = pk2(f1.x, f2.y);
        sNB[p] = pk2(n0, n1);
    }

    unsigned long long qx2[QPT], qy2[QPT], qz2[QPT], nqq2[QPT];
    float best[QPT];
    #pragma unroll
    for (int k = 0; k < QPT; ++k) {
        const float* qp = out_xyz + ((size_t)b * MM + qbase + k * 32 + lane) * 3;
        float x = qp[0], y = qp[1], z = qp[2];
        float nq = -0.5f * fmaf(x, x, fmaf(y, y, z * z));
        qx2[k] = pk2(x, x); qy2[k] = pk2(y, y); qz2[k] = pk2(z, z);
        nqq2[k] = pk2(nq, nq);
        best[k] = -3.4e38f;
    }
    __syncthreads();

    const int pw = w * PPW;
    const int grp = lane >> 2;

    int bst[QPT];
    #pragma unroll
    for (int k = 0; k < QPT; ++k) bst[k] = 0;

    #pragma unroll 1
    for (int ch = 0; ch < NCHUNK; ++ch) {
        float old[QPT];
        #pragma unroll
        for (int k = 0; k < QPT; ++k) old[k] = best[k];
        #pragma unroll
        for (int pp = 0; pp < CHUNK_P; ++pp) {
            int p = pw + ch * CHUNK_P + pp;
            unsigned long long sx2 = sX[p], sy2 = sY[p];
            unsigned long long sz2 = sZ[p], nb2 = sNB[p];
            float cv0 = -3.4e38f, cv1 = -3.4e38f;
            #pragma unroll
            for (int k = 0; k < QPT; ++k) {
                float v0, v1;
                ffma2v(v0, v1, qz2[k], sz2, nb2, qy2[k], sy2,
                       qx2[k], sx2, nqq2[k]);
                best[k] = fmaxf(best[k], fmaxf(v0, v1));
                cv0 = fmaxf(cv0, v0);
                cv1 = fmaxf(cv1, v1);
            }
            // per-candidate max over 4-lane group (2 rounds)
            cv0 = fmaxf(cv0, __shfl_xor_sync(0xffffffffu, cv0, 1));
            cv1 = fmaxf(cv1, __shfl_xor_sync(0xffffffffu, cv1, 1));
            cv0 = fmaxf(cv0, __shfl_xor_sync(0xffffffffu, cv0, 2));
            cv1 = fmaxf(cv1, __shfl_xor_sync(0xffffffffu, cv1, 2));
            if ((lane & 3) == 0) {
                int cpair = split * (CPB / 2) + w * (CPW / 2) + (p - pw);
                g_part_n[(size_t)(qb * NGRP + grp) * NPAIR_G +
                         (size_t)b * (NN / 2) + cpair] =
                    make_float2(cv0, cv1);
            }
        }
        #pragma unroll
        for (int k = 0; k < QPT; ++k)
            if (best[k] > old[k]) bst[k] = ch;
    }

    // exact first-index recovery in winning 8-candidate window
    const float* fX  = (const float*)sX;
    const float* fY  = (const float*)sY;
    const float* fZ  = (const float*)sZ;
    const float* fNB = (const float*)sNB;
    #pragma unroll 1
    for (int k = 0; k < QPT; ++k) {
        float qx = lo32(qx2[k]), qy = lo32(qy2[k]), qz = lo32(qz2[k]);
        float nq = lo32(nqq2[k]);
        float bestf = best[k];
        int base = w * CPW + bst[k] * (CHUNK_P * 2);
        int found = 0;
        #pragma unroll
        for (int j = CHUNK_P * 2 - 1; j >= 0; --j) {  // descending: first match wins
            float t = fmaf(qx, fX[base + j],
                      fmaf(qy, fY[base + j],
                      fmaf(qz, fZ[base + j], fNB[base + j])));
            float v = __fadd_rn(t, nq);
            found = (v == bestf) ? j : found;
        }
        float dsq = fmaxf(-2.0f * bestf, 0.0f);
        unsigned gidx = (unsigned)(cbase + base + found);
        unsigned long long key =
            ((unsigned long long)__float_as_uint(dsq) << 32) | gidx;
        atomicMin(&skey[k * 32 + lane], key);
    }
    __syncthreads();
    g_part_m[(size_t)split * (BB * MM) + (size_t)b * MM + qbase + tid] =
        skey[tid];
}

// -----------------------------------------------------------------------------
__device__ __forceinline__ float warp_sum(float v) {
    #pragma unroll
    for (int o = 16; o; o >>= 1) v += __shfl_xor_sync(0xffffffffu, v, o);
    return v;
}

// fused loss: blocks [0,NLOSSM) = m-path (warp per query), rest = n-path
__global__ void loss_kernel(const float* __restrict__ in_rot,
                            const float* __restrict__ in_scale,
                            const float* __restrict__ in_op,
                            const float* __restrict__ in_dc,
                            const float* __restrict__ in_rest,
                            const float* __restrict__ out_rot,
                            const float* __restrict__ out_scale,
                            const float* __restrict__ out_op,
                            const float* __restrict__ out_dc,
                            const float* __restrict__ out_rest) {
    __shared__ float sw[8];
    const int lane = threadIdx.x & 31, w = threadIdx.x >> 5;
    float c = 0.0f;

    if (blockIdx.x < NLOSSM) {
        const size_t om = (size_t)blockIdx.x * 8 + w;   // global over B*M
        const int b = (int)(om / MM);

        unsigned long long key = 0xFFFFFFFFFFFFFFFFull;
        if (lane < NSPLIT) key = g_part_m[(size_t)lane * (BB * MM) + om];
        #pragma unroll
        for (int o = 4; o; o >>= 1) {
            unsigned long long other = __shfl_xor_sync(0xffffffffu, key, o);
            key = (other < key) ? other : key;
        }
        key = __shfl_sync(0xffffffffu, key, 0);

        float d = sqrtf(__uint_as_float((unsigned)(key >> 32)));
        unsigned idx = (unsigned)(key & 0xFFFFFFFFu);
        const size_t ii = (size_t)b * NN + idx;

        const float W_POSM = 0.5f / (BB * MM);
        const float W_ROT  = 0.5f / (BB * MM);
        const float W_SC   = 0.5f / (BB * MM * 3);
        const float W_OP   = 0.3f / (BB * MM);
        const float W_DC   = 0.2f / (BB * MM * 3);
        const float W_RST  = 0.2f / (BB * MM * 45);

        c = W_RST * fabsf(out_rest[om * 45 + lane] - in_rest[ii * 45 + lane]);
        if (lane < 13)
            c += W_RST * fabsf(out_rest[om * 45 + 32 + lane] -
                               in_rest[ii * 45 + 32 + lane]);
        if (lane < 3) {
            c += W_SC * fabsf(out_scale[om * 3 + lane] - in_scale[ii * 3 + lane]);
            c += W_DC * fabsf(out_dc[om * 3 + lane]    - in_dc[ii * 3 + lane]);
        }
        if (lane == 0) {
            float dot = 0.0f;
            #pragma unroll
            for (int j = 0; j < 4; ++j)
                dot = fmaf(out_rot[om * 4 + j], in_rot[ii * 4 + j], dot);
            c += W_ROT * (1.0f - fabsf(dot));
            c += W_OP * fabsf(out_op[om] - in_op[ii]);
            c += W_POSM * d;
        }
    } else {
        // candidate-pair path: merge 256 group partials, two candidates
        const size_t i =
            (size_t)(blockIdx.x - NLOSSM) * TPB + threadIdx.x;  // over NPAIR_G
        float vm0 = -3.4e38f, vm1 = -3.4e38f;
        #pragma unroll 8
        for (int s = 0; s < QB * NGRP; ++s) {
            float2 v = g_part_n[(size_t)s * NPAIR_G + i];
            vm0 = fmaxf(vm0, v.x);
            vm1 = fmaxf(vm1, v.y);
        }
        float d0 = sqrtf(fmaxf(-2.0f * vm0, 0.0f));
        float d1 = sqrtf(fmaxf(-2.0f * vm1, 0.0f));
        c = (0.5f / (BB * NN)) * (d0 + d1);
    }

    c = warp_sum(c);
    if (lane == 0) sw[w] = c;
    __syncthreads();
    if (threadIdx.x == 0) {
        float t = 0.0f;
        #pragma unroll
        for (int j = 0; j < 8; ++j) t += sw[j];
        g_lsum[blockIdx.x] = t;
    }
}

__global__ void final_kernel(float* __restrict__ out) {
    __shared__ float sw[8];
    const int lane = threadIdx.x & 31, w = threadIdx.x >> 5;
    float v = 0.0f;
    for (int i = threadIdx.x; i < NLOSS; i += TPB) v += g_lsum[i];
    v = warp_sum(v);
    if (lane == 0) sw[w] = v;
    __syncthreads();
    if (threadIdx.x == 0) {
        float t = 0.0f;
        #pragma unroll
        for (int j = 0; j < 8; ++j) t += sw[j];
        out[0] = t;
    }
}

// -----------------------------------------------------------------------------
extern "C" void kernel_launch(void* const* d_in, const int* in_sizes, int n_in,
                              void* d_out, int out_size) {
    const float* in_xyz    = (const float*)d_in[0];
    const float* in_rot    = (const float*)d_in[1];
    const float* in_scale  = (const float*)d_in[2];
    const float* in_op     = (const float*)d_in[3];
    const float* in_dc     = (const float*)d_in[4];
    const float* in_rest   = (const float*)d_in[5];
    const float* out_xyz   = (const float*)d_in[6];
    const float* out_rot   = (const float*)d_in[7];
    const float* out_scale = (const float*)d_in[8];
    const float* out_op    = (const float*)d_in[9];
    const float* out_dc    = (const float*)d_in[10];
    const float* out_rest  = (const float*)d_in[11];
    float* out = (float*)d_out;

    dim3 g(QB, NSPLIT, BB);
    dist_kernel<<<g, TPB>>>(out_xyz, in_xyz);

    loss_kernel<<<NLOSS, TPB>>>(in_rot, in_scale, in_op, in_dc, in_rest,
                                out_rot, out_scale, out_op, out_dc, out_rest);
    final_kernel<<<1, TPB>>>(out);
}

// round 11
// speedup vs baseline: 1.2284x; 1.2284x over previous
#include <cuda_runtime.h>
#include <math.h>

#define BB 2
#define MM 8192
#define NN 8192
#define TPB 256
#define NSPLIT 4
#define QPT 8                  // queries per thread (8 warps x 32 lanes)
#define CPB 2048               // candidates per block tile
#define PPB (CPB/2)            // pairs per block tile = 1024
#define NW 8
#define CPW (CPB/NW)           // candidates per warp = 256
#define PPW (PPB/NW)           // pairs per warp = 128
#define CHUNK_P 4              // pairs per tracking chunk (8 candidates)
#define NCHUNK (PPW/CHUNK_P)   // 32 chunks
#define NLOSSM (BB*MM/8)       // 2048 m-loss blocks (warp per query)
#define NLOSSN (BB*NN/TPB)     // 64 n-loss blocks
#define NLOSS  (NLOSSM+NLOSSN) // 2112

// ---- scratch (owned slots, no init required) --------------------------------
__device__ unsigned long long g_part_m[NSPLIT * BB * MM]; // (dsq_bits<<32)|idx
__device__ unsigned int       g_part_n[NSPLIT * BB * NN]; // dsq bits
__device__ float              g_lsum[NLOSS];              // per-loss-block sums

// ---- packed f32x2 helpers ---------------------------------------------------
__device__ __forceinline__ unsigned long long pk2(float lo, float hi) {
    unsigned long long r;
    asm("mov.b64 %0, {%1,%2};" : "=l"(r) : "f"(lo), "f"(hi));
    return r;
}
__device__ __forceinline__ float lo32(unsigned long long v) {
    return __uint_as_float((unsigned)(v & 0xFFFFFFFFull));
}
__device__ __forceinline__ float hi32(unsigned long long v) {
    return __uint_as_float((unsigned)(v >> 32));
}
// single packed fma: d = a*b + c (both halves)
__device__ __forceinline__ unsigned long long fma2(
    unsigned long long a, unsigned long long b, unsigned long long c) {
    unsigned long long d;
    asm("fma.rn.f32x2 %0, %1, %2, %3;" : "=l"(d) : "l"(a), "l"(b), "l"(c));
    return d;
}

// ---- fused distance scan: dir 0 = out->in (argmin), dir 1 = in->out (min) ---
__global__ void __launch_bounds__(TPB, 2)
dist_kernel(const float* __restrict__ out_xyz,
            const float* __restrict__ in_xyz) {
    __shared__ unsigned long long sX[PPB], sY[PPB], sZ[PPB], sNB[PPB];
    __shared__ unsigned long long skey[TPB];

    const int tid = threadIdx.x;
    const int lane = tid & 31, w = tid >> 5;
    const int dir = blockIdx.z & 1;
    const int b = blockIdx.z >> 1;
    const float* qpts = dir ? in_xyz : out_xyz;
    const float* cpts = dir ? out_xyz : in_xyz;
    const int split = blockIdx.y;
    const int cbase = split * CPB;
    const int qbase = blockIdx.x * TPB;

    skey[tid] = 0xFFFFFFFFFFFFFFFFull;

    // candidate tile, packed two-per-u64 (even, odd)
    for (int p = tid; p < PPB; p += TPB) {
        const float2* cp =
            (const float2*)(cpts + ((size_t)b * NN + cbase + 2 * p) * 3);
        float2 f0 = __ldg(cp + 0);   // x0 y0
        float2 f1 = __ldg(cp + 1);   // z0 x1
        float2 f2 = __ldg(cp + 2);   // y1 z1
        float n0 = -0.5f * fmaf(f0.x, f0.x, fmaf(f0.y, f0.y, f1.x * f1.x));
        float n1 = -0.5f * fmaf(f1.y, f1.y, fmaf(f2.x, f2.x, f2.y * f2.y));
        sX[p]  = pk2(f0.x, f1.y);
        sY[p]  = pk2(f0.y, f2.x);
        sZ[p]  = pk2(f1.x, f2.y);
        sNB[p] = pk2(n0, n1);
    }

    unsigned long long qx2[QPT], qy2[QPT], qz2[QPT];
    float best[QPT];
    #pragma unroll
    for (int k = 0; k < QPT; ++k) {
        const float* qp = qpts + ((size_t)b * MM + qbase + k * 32 + lane) * 3;
        float x = qp[0], y = qp[1], z = qp[2];
        qx2[k] = pk2(x, x); qy2[k] = pk2(y, y); qz2[k] = pk2(z, z);
        best[k] = -3.4e38f;
    }
    __syncthreads();

    const int pw = w * PPW;

    if (dir == 0) {
        // ---- out->in: max-e with chunk tracking for exact argmin ------------
        int bst[QPT];
        #pragma unroll
        for (int k = 0; k < QPT; ++k) bst[k] = 0;

        for (int ch = 0; ch < NCHUNK; ++ch) {
            float old[QPT];
            #pragma unroll
            for (int k = 0; k < QPT; ++k) old[k] = best[k];
            #pragma unroll
            for (int pp = 0; pp < CHUNK_P; ++pp) {
                int p = pw + ch * CHUNK_P + pp;
                unsigned long long sx2 = sX[p], sy2 = sY[p];
                unsigned long long sz2 = sZ[p], nb2 = sNB[p];
                unsigned long long t2[QPT];
                // component-major: consecutive ops share candidate operands
                #pragma unroll
                for (int k = 0; k < QPT; ++k) t2[k] = fma2(qz2[k], sz2, nb2);
                #pragma unroll
                for (int k = 0; k < QPT; ++k) t2[k] = fma2(qy2[k], sy2, t2[k]);
                #pragma unroll
                for (int k = 0; k < QPT; ++k) t2[k] = fma2(qx2[k], sx2, t2[k]);
                #pragma unroll
                for (int k = 0; k < QPT; ++k)
                    best[k] = fmaxf(best[k],
                                    fmaxf(lo32(t2[k]), hi32(t2[k])));
            }
            #pragma unroll
            for (int k = 0; k < QPT; ++k)
                if (best[k] > old[k]) bst[k] = ch;
        }

        // exact first-index recovery in winning 8-candidate window
        const float* fX  = (const float*)sX;
        const float* fY  = (const float*)sY;
        const float* fZ  = (const float*)sZ;
        const float* fNB = (const float*)sNB;
        #pragma unroll 1
        for (int k = 0; k < QPT; ++k) {
            float qx = lo32(qx2[k]), qy = lo32(qy2[k]), qz = lo32(qz2[k]);
            float bestf = best[k];
            int base = w * CPW + bst[k] * (CHUNK_P * 2);
            int found = 0;
            #pragma unroll
            for (int j = CHUNK_P * 2 - 1; j >= 0; --j) {  // descending: first match wins
                float e = fmaf(qx, fX[base + j],
                          fmaf(qy, fY[base + j],
                          fmaf(qz, fZ[base + j], fNB[base + j])));
                found = (e == bestf) ? j : found;
            }
            float so  = fmaf(qx, qx, fmaf(qy, qy, qz * qz));
            float dsq = fmaxf(fmaf(-2.0f, bestf, so), 0.0f);
            unsigned gidx = (unsigned)(cbase + base + found);
            unsigned long long key =
                ((unsigned long long)__float_as_uint(dsq) << 32) | gidx;
            atomicMin(&skey[k * 32 + lane], key);
        }
        __syncthreads();
        g_part_m[(size_t)split * (BB * MM) + (size_t)b * MM + qbase + tid] =
            skey[tid];
    } else {
        // ---- in->out: min distance only, component-major ---------------------
        #pragma unroll 4
        for (int p = pw; p < pw + PPW; ++p) {
            unsigned long long sx2 = sX[p], sy2 = sY[p];
            unsigned long long sz2 = sZ[p], nb2 = sNB[p];
            unsigned long long t2[QPT];
            #pragma unroll
            for (int k = 0; k < QPT; ++k) t2[k] = fma2(qz2[k], sz2, nb2);
            #pragma unroll
            for (int k = 0; k < QPT; ++k) t2[k] = fma2(qy2[k], sy2, t2[k]);
            #pragma unroll
            for (int k = 0; k < QPT; ++k) t2[k] = fma2(qx2[k], sx2, t2[k]);
            #pragma unroll
            for (int k = 0; k < QPT; ++k)
                best[k] = fmaxf(best[k], fmaxf(lo32(t2[k]), hi32(t2[k])));
        }
        #pragma unroll
        for (int k = 0; k < QPT; ++k) {
            float qx = lo32(qx2[k]), qy = lo32(qy2[k]), qz = lo32(qz2[k]);
            float so  = fmaf(qx, qx, fmaf(qy, qy, qz * qz));
            float dsq = fmaxf(fmaf(-2.0f, best[k], so), 0.0f);
            atomicMin(&skey[k * 32 + lane],
                      (unsigned long long)__float_as_uint(dsq) << 32);
        }
        __syncthreads();
        g_part_n[(size_t)split * (BB * NN) + (size_t)b * NN + qbase + tid] =
            (unsigned)(skey[tid] >> 32);
    }
}

// -----------------------------------------------------------------------------
__device__ __forceinline__ float warp_sum(float v) {
    #pragma unroll
    for (int o = 16; o; o >>= 1) v += __shfl_xor_sync(0xffffffffu, v, o);
    return v;
}

// fused loss: blocks [0,NLOSSM) = m-path (warp/query), [NLOSSM,NLOSS) = n-path
__global__ void loss_kernel(const float* __restrict__ in_rot,
                            const float* __restrict__ in_scale,
                            const float* __restrict__ in_op,
                            const float* __restrict__ in_dc,
                            const float* __restrict__ in_rest,
                            const float* __restrict__ out_rot,
                            const float* __restrict__ out_scale,
                            const float* __restrict__ out_op,
                            const float* __restrict__ out_dc,
                            const float* __restrict__ out_rest) {
    __shared__ float sw[8];
    const int lane = threadIdx.x & 31, w = threadIdx.x >> 5;
    float c = 0.0f;

    if (blockIdx.x < NLOSSM) {
        const size_t om = (size_t)blockIdx.x * 8 + w;   // global over B*M
        const int b = (int)(om / MM);

        // min over NSPLIT partials (lanes 0..NSPLIT-1 hold them)
        unsigned long long key = 0xFFFFFFFFFFFFFFFFull;
        if (lane < NSPLIT) key = g_part_m[(size_t)lane * (BB * MM) + om];
        #pragma unroll
        for (int o = 4; o; o >>= 1) {
            unsigned long long other = __shfl_xor_sync(0xffffffffu, key, o);
            key = (other < key) ? other : key;
        }
        key = __shfl_sync(0xffffffffu, key, 0);

        float d = sqrtf(__uint_as_float((unsigned)(key >> 32)));
        unsigned idx = (unsigned)(key & 0xFFFFFFFFu);
        const size_t ii = (size_t)b * NN + idx;

        const float W_POSM = 0.5f / (BB * MM);
        const float W_ROT  = 0.5f / (BB * MM);
        const float W_SC   = 0.5f / (BB * MM * 3);
        const float W_OP   = 0.3f / (BB * MM);
        const float W_DC   = 0.2f / (BB * MM * 3);
        const float W_RST  = 0.2f / (BB * MM * 45);

        c = W_RST * fabsf(out_rest[om * 45 + lane] - in_rest[ii * 45 + lane]);
        if (lane < 13)
            c += W_RST * fabsf(out_rest[om * 45 + 32 + lane] -
                               in_rest[ii * 45 + 32 + lane]);
        if (lane < 3) {
            c += W_SC * fabsf(out_scale[om * 3 + lane] - in_scale[ii * 3 + lane]);
            c += W_DC * fabsf(out_dc[om * 3 + lane]    - in_dc[ii * 3 + lane]);
        }
        if (lane == 0) {
            float dot = 0.0f;
            #pragma unroll
            for (int j = 0; j < 4; ++j)
                dot = fmaf(out_rot[om * 4 + j], in_rot[ii * 4 + j], dot);
            c += W_ROT * (1.0f - fabsf(dot));
            c += W_OP * fabsf(out_op[om] - in_op[ii]);
            c += W_POSM * d;
        }
    } else {
        const size_t i =
            (size_t)(blockIdx.x - NLOSSM) * TPB + threadIdx.x;  // over B*N
        unsigned mn = 0xFFFFFFFFu;
        #pragma unroll
        for (int s = 0; s < NSPLIT; ++s) {
            unsigned v = g_part_n[(size_t)s * (BB * NN) + i];
            mn = (v < mn) ? v : mn;
        }
        c = (0.5f / (BB * NN)) * sqrtf(__uint_as_float(mn));
    }

    c = warp_sum(c);
    if (lane == 0) sw[w] = c;
    __syncthreads();
    if (threadIdx.x == 0) {
        float t = 0.0f;
        #pragma unroll
        for (int j = 0; j < 8; ++j) t += sw[j];
        g_lsum[blockIdx.x] = t;
    }
}

__global__ void final_kernel(float* __restrict__ out) {
    __shared__ float sw[8];
    const int lane = threadIdx.x & 31, w = threadIdx.x >> 5;
    float v = 0.0f;
    for (int i = threadIdx.x; i < NLOSS; i += TPB) v += g_lsum[i];
    v = warp_sum(v);
    if (lane == 0) sw[w] = v;
    __syncthreads();
    if (threadIdx.x == 0) {
        float t = 0.0f;
        #pragma unroll
        for (int j = 0; j < 8; ++j) t += sw[j];
        out[0] = t;
    }
}

// -----------------------------------------------------------------------------
extern "C" void kernel_launch(void* const* d_in, const int* in_sizes, int n_in,
                              void* d_out, int out_size) {
    const float* in_xyz    = (const float*)d_in[0];
    const float* in_rot    = (const float*)d_in[1];
    const float* in_scale  = (const float*)d_in[2];
    const float* in_op     = (const float*)d_in[3];
    const float* in_dc     = (const float*)d_in[4];
    const float* in_rest   = (const float*)d_in[5];
    const float* out_xyz   = (const float*)d_in[6];
    const float* out_rot   = (const float*)d_in[7];
    const float* out_scale = (const float*)d_in[8];
    const float* out_op    = (const float*)d_in[9];
    const float* out_dc    = (const float*)d_in[10];
    const float* out_rest  = (const float*)d_in[11];
    float* out = (float*)d_out;

    dim3 g(MM / TPB, NSPLIT, BB * 2);
    dist_kernel<<<g, TPB>>>(out_xyz, in_xyz);

    loss_kernel<<<NLOSS, TPB>>>(in_rot, in_scale, in_op, in_dc, in_rest,
                                out_rot, out_scale, out_op, out_dc, out_rest);
    final_kernel<<<1, TPB>>>(out);
}